// round 1
// baseline (speedup 1.0000x reference)
#include <cuda_runtime.h>
#include <cstdint>

// Skeleton FK: angles [B,24,6] f32, xyz [1,24,3] f32 -> out [B,24,3] f32
//
// Tree (joint -> parent):
//  1..3 -> 0 ; 4->1 5->2 6->3 ; 7->4 8->5 9->6 ; 10->7 11->8 ; 12,13,14 -> 9
//  15->12 ; 16->13 17->14 ; 18->16 19->17 ; 20->18 21->19 ; 22->20 23->21
//
// Decomposed into parent-consecutive chains from branch points 0 and 9:
//  root: 0
//  c1: 1,4,7,10      (from 0)
//  c2: 2,5,8,11      (from 0)
//  c3: 3,6,9         (from 0)   -> save R9,T9
//  c4: 12,15         (from 9)
//  c5: 13,16,18,20,22 (from 9)
//  c6: 14,17,19,21,23 (from 9)

#define NJ 24
#define TPB 64
#define ROW 145   // 144 floats per batch row + 1 pad (odd mod 32 -> conflict-free)

__device__ __forceinline__ void rot6d(const float* __restrict__ s, float R[9]) {
    float a1x = s[0], a1y = s[1], a1z = s[2];
    float a2x = s[3], a2y = s[4], a2z = s[5];
    float inv1 = rsqrtf(fmaf(a1x, a1x, fmaf(a1y, a1y, a1z * a1z)));
    float b1x = a1x * inv1, b1y = a1y * inv1, b1z = a1z * inv1;
    float d = fmaf(b1x, a2x, fmaf(b1y, a2y, b1z * a2z));
    float c2x = fmaf(-d, b1x, a2x);
    float c2y = fmaf(-d, b1y, a2y);
    float c2z = fmaf(-d, b1z, a2z);
    float inv2 = rsqrtf(fmaf(c2x, c2x, fmaf(c2y, c2y, c2z * c2z)));
    float b2x = c2x * inv2, b2y = c2y * inv2, b2z = c2z * inv2;
    // b3 = b1 x b2
    float b3x = fmaf(b1y, b2z, -b1z * b2y);
    float b3y = fmaf(b1z, b2x, -b1x * b2z);
    float b3z = fmaf(b1x, b2y, -b1y * b2x);
    R[0] = b1x; R[1] = b1y; R[2] = b1z;
    R[3] = b2x; R[4] = b2y; R[5] = b2z;
    R[6] = b3x; R[7] = b3y; R[8] = b3z;
}

// One FK step: child c with parent p. R,T updated in place; T_c written back
// into the (already consumed) angle slot of joint c in this thread's smem row.
__device__ __forceinline__ void fk_step(float* __restrict__ srow,
                                        const float* __restrict__ xyz,
                                        int c, int p,
                                        float R[9], float T[3]) {
    float rc[9];
    rot6d(srow + c * 6, rc);
    float ox = __ldg(xyz + c * 3 + 0) - __ldg(xyz + p * 3 + 0);
    float oy = __ldg(xyz + c * 3 + 1) - __ldg(xyz + p * 3 + 1);
    float oz = __ldg(xyz + c * 3 + 2) - __ldg(xyz + p * 3 + 2);
    // t3 = rc @ off
    float t3x = fmaf(rc[0], ox, fmaf(rc[1], oy, rc[2] * oz));
    float t3y = fmaf(rc[3], ox, fmaf(rc[4], oy, rc[5] * oz));
    float t3z = fmaf(rc[6], ox, fmaf(rc[7], oy, rc[8] * oz));
    // T_new = R @ t3 + T
    float Tn0 = fmaf(R[0], t3x, fmaf(R[1], t3y, fmaf(R[2], t3z, T[0])));
    float Tn1 = fmaf(R[3], t3x, fmaf(R[4], t3y, fmaf(R[5], t3z, T[1])));
    float Tn2 = fmaf(R[6], t3x, fmaf(R[7], t3y, fmaf(R[8], t3z, T[2])));
    // R_new = R @ rc
    float Rn[9];
#pragma unroll
    for (int r = 0; r < 3; r++) {
#pragma unroll
        for (int k = 0; k < 3; k++) {
            Rn[r * 3 + k] = fmaf(R[r * 3 + 0], rc[0 * 3 + k],
                            fmaf(R[r * 3 + 1], rc[1 * 3 + k],
                                 R[r * 3 + 2] * rc[2 * 3 + k]));
        }
    }
#pragma unroll
    for (int i = 0; i < 9; i++) R[i] = Rn[i];
    T[0] = Tn0; T[1] = Tn1; T[2] = Tn2;
    srow[c * 6 + 0] = Tn0;
    srow[c * 6 + 1] = Tn1;
    srow[c * 6 + 2] = Tn2;
}

__global__ __launch_bounds__(TPB) void skeleton_fk_kernel(
    const float* __restrict__ angles,
    const float* __restrict__ xyz,
    float* __restrict__ out,
    int B)
{
    __shared__ float smem[TPB * ROW];

    const int t = threadIdx.x;
    const int b0 = blockIdx.x * TPB;
    const int nvalid = min(TPB, B - b0);

    // ---- Phase 1: coalesced load angles -> padded smem rows ----
    // Each batch row = 144 floats = 36 float4.
    {
        const float4* __restrict__ g4 =
            reinterpret_cast<const float4*>(angles) + (size_t)b0 * 36;
        const int total4 = nvalid * 36;
#pragma unroll
        for (int it = 0; it < 36; it++) {
            int idx = it * TPB + t;
            if (idx < total4) {
                float4 v = g4[idx];
                int row  = idx / 36;
                int col4 = idx % 36;
                float* dst = smem + row * ROW + col4 * 4;
                dst[0] = v.x; dst[1] = v.y; dst[2] = v.z; dst[3] = v.w;
            }
        }
    }
    __syncthreads();

    // ---- Phase 2: per-thread tree FK ----
    if (t < nvalid) {
        float* srow = smem + t * ROW;

        float R0[9], T0[3];
        rot6d(srow, R0);
        {
            float rx = __ldg(xyz + 0), ry = __ldg(xyz + 1), rz = __ldg(xyz + 2);
            T0[0] = fmaf(R0[0], rx, fmaf(R0[1], ry, R0[2] * rz));
            T0[1] = fmaf(R0[3], rx, fmaf(R0[4], ry, R0[5] * rz));
            T0[2] = fmaf(R0[6], rx, fmaf(R0[7], ry, R0[8] * rz));
        }
        srow[0] = T0[0]; srow[1] = T0[1]; srow[2] = T0[2];

        float R[9], T[3], R9[9], T9[3];

        // chain 1: 1,4,7,10
        {
            const int cs[4] = {1, 4, 7, 10}, ps[4] = {0, 1, 4, 7};
#pragma unroll
            for (int i = 0; i < 9; i++) R[i] = R0[i];
#pragma unroll
            for (int i = 0; i < 3; i++) T[i] = T0[i];
#pragma unroll
            for (int i = 0; i < 4; i++) fk_step(srow, xyz, cs[i], ps[i], R, T);
        }
        // chain 2: 2,5,8,11
        {
            const int cs[4] = {2, 5, 8, 11}, ps[4] = {0, 2, 5, 8};
#pragma unroll
            for (int i = 0; i < 9; i++) R[i] = R0[i];
#pragma unroll
            for (int i = 0; i < 3; i++) T[i] = T0[i];
#pragma unroll
            for (int i = 0; i < 4; i++) fk_step(srow, xyz, cs[i], ps[i], R, T);
        }
        // chain 3: 3,6,9  (save state at joint 9)
        {
            const int cs[3] = {3, 6, 9}, ps[3] = {0, 3, 6};
#pragma unroll
            for (int i = 0; i < 9; i++) R[i] = R0[i];
#pragma unroll
            for (int i = 0; i < 3; i++) T[i] = T0[i];
#pragma unroll
            for (int i = 0; i < 3; i++) fk_step(srow, xyz, cs[i], ps[i], R, T);
#pragma unroll
            for (int i = 0; i < 9; i++) R9[i] = R[i];
#pragma unroll
            for (int i = 0; i < 3; i++) T9[i] = T[i];
        }
        // chain 4: 12,15
        {
            const int cs[2] = {12, 15}, ps[2] = {9, 12};
#pragma unroll
            for (int i = 0; i < 9; i++) R[i] = R9[i];
#pragma unroll
            for (int i = 0; i < 3; i++) T[i] = T9[i];
#pragma unroll
            for (int i = 0; i < 2; i++) fk_step(srow, xyz, cs[i], ps[i], R, T);
        }
        // chain 5: 13,16,18,20,22
        {
            const int cs[5] = {13, 16, 18, 20, 22}, ps[5] = {9, 13, 16, 18, 20};
#pragma unroll
            for (int i = 0; i < 9; i++) R[i] = R9[i];
#pragma unroll
            for (int i = 0; i < 3; i++) T[i] = T9[i];
#pragma unroll
            for (int i = 0; i < 5; i++) fk_step(srow, xyz, cs[i], ps[i], R, T);
        }
        // chain 6: 14,17,19,21,23
        {
            const int cs[5] = {14, 17, 19, 21, 23}, ps[5] = {9, 14, 17, 19, 21};
#pragma unroll
            for (int i = 0; i < 9; i++) R[i] = R9[i];
#pragma unroll
            for (int i = 0; i < 3; i++) T[i] = T9[i];
#pragma unroll
            for (int i = 0; i < 5; i++) fk_step(srow, xyz, cs[i], ps[i], R, T);
        }
    }
    __syncthreads();

    // ---- Phase 3: coalesced store out <- smem (T lives at angle slot c*6) ----
    // Each batch row of output = 72 floats = 18 float4.
    {
        float4* __restrict__ o4 =
            reinterpret_cast<float4*>(out) + (size_t)b0 * 18;
        const int total4 = nvalid * 18;
#pragma unroll
        for (int it = 0; it < 18; it++) {
            int idx = it * TPB + t;
            if (idx < total4) {
                int row = idx / 18;
                int j   = (idx % 18) * 4;
                const float* srow = smem + row * ROW;
                float4 v;
                // component jj -> joint jj/3, coord jj%3 -> smem slot joint*6 + coord
                int j0 = j + 0, j1 = j + 1, j2 = j + 2, j3 = j + 3;
                v.x = srow[(j0 / 3) * 6 + (j0 % 3)];
                v.y = srow[(j1 / 3) * 6 + (j1 % 3)];
                v.z = srow[(j2 / 3) * 6 + (j2 % 3)];
                v.w = srow[(j3 / 3) * 6 + (j3 % 3)];
                o4[idx] = v;
            }
        }
    }
}

extern "C" void kernel_launch(void* const* d_in, const int* in_sizes, int n_in,
                              void* d_out, int out_size) {
    const float* angles = (const float*)d_in[0];
    const float* xyz    = (const float*)d_in[1];
    float* out          = (float*)d_out;
    const int B = in_sizes[0] / (NJ * 6);
    const int blocks = (B + TPB - 1) / TPB;
    skeleton_fk_kernel<<<blocks, TPB>>>(angles, xyz, out, B);
}

// round 2
// speedup vs baseline: 1.0134x; 1.0134x over previous
#include <cuda_runtime.h>
#include <cstdint>

// Skeleton FK: angles [B,24,6] f32, xyz [1,24,3] f32 -> out [B,24,3] f32
//
// 4 warps per block; warp w has role w (A/B/C/D). Lane L of every warp works
// on batch row (blockIdx.x*32 + L). Roles partition the joint tree:
//   A: root(store) + chain 1,4,7,10 + chain 2,5,8,11          (stores 9)
//   B: root + 3,6,9 (store) + 12,15 (store)                   (stores 5)
//   C: root + 3,6,9 (recompute) + 13,16,18,20,22 (store)      (stores 5)
//   D: root + 3,6,9 (recompute) + 14,17,19,21,23 (store)      (stores 5)
// Warp-uniform branching -> no divergence. Per-thread state = R,T (+R0,T0 in A).

#define TPB  128
#define ROWS 32
#define RROW 217          // 144 angle floats + 72 out floats + 1 pad (odd mod 32)
#define XOFF_SZ 76        // 24*3 offsets + pad

__constant__ int c_parent[24] = {-1, 0, 0, 0, 1, 2, 3, 4, 5, 6, 7, 8,
                                  9, 9, 9, 12, 13, 14, 16, 17, 18, 19, 20, 21};

__device__ __forceinline__ void rot6d(const float* __restrict__ s, float R[9]) {
    float a1x = s[0], a1y = s[1], a1z = s[2];
    float a2x = s[3], a2y = s[4], a2z = s[5];
    float inv1 = rsqrtf(fmaf(a1x, a1x, fmaf(a1y, a1y, a1z * a1z)));
    float b1x = a1x * inv1, b1y = a1y * inv1, b1z = a1z * inv1;
    float d = fmaf(b1x, a2x, fmaf(b1y, a2y, b1z * a2z));
    float c2x = fmaf(-d, b1x, a2x);
    float c2y = fmaf(-d, b1y, a2y);
    float c2z = fmaf(-d, b1z, a2z);
    float inv2 = rsqrtf(fmaf(c2x, c2x, fmaf(c2y, c2y, c2z * c2z)));
    float b2x = c2x * inv2, b2y = c2y * inv2, b2z = c2z * inv2;
    float b3x = fmaf(b1y, b2z, -b1z * b2y);
    float b3y = fmaf(b1z, b2x, -b1x * b2z);
    float b3z = fmaf(b1x, b2y, -b1y * b2x);
    R[0] = b1x; R[1] = b1y; R[2] = b1z;
    R[3] = b2x; R[4] = b2y; R[5] = b2z;
    R[6] = b3x; R[7] = b3y; R[8] = b3z;
}

// Root joint: R = rot6d(angles0), T = R @ xyz0
__device__ __forceinline__ void fk_root(const float* __restrict__ srow,
                                        float* __restrict__ orow,
                                        const float* __restrict__ xoff,
                                        float R[9], float T[3], bool store) {
    rot6d(srow, R);
    float rx = xoff[0], ry = xoff[1], rz = xoff[2];
    T[0] = fmaf(R[0], rx, fmaf(R[1], ry, R[2] * rz));
    T[1] = fmaf(R[3], rx, fmaf(R[4], ry, R[5] * rz));
    T[2] = fmaf(R[6], rx, fmaf(R[7], ry, R[8] * rz));
    if (store) { orow[0] = T[0]; orow[1] = T[1]; orow[2] = T[2]; }
}

// One FK step for child joint c: updates R,T in place; optionally stores T.
__device__ __forceinline__ void fk_step(const float* __restrict__ srow,
                                        float* __restrict__ orow,
                                        const float* __restrict__ xoff,
                                        int c, float R[9], float T[3], bool store) {
    float rc[9];
    rot6d(srow + c * 6, rc);
    float ox = xoff[c * 3 + 0], oy = xoff[c * 3 + 1], oz = xoff[c * 3 + 2];
    float t3x = fmaf(rc[0], ox, fmaf(rc[1], oy, rc[2] * oz));
    float t3y = fmaf(rc[3], ox, fmaf(rc[4], oy, rc[5] * oz));
    float t3z = fmaf(rc[6], ox, fmaf(rc[7], oy, rc[8] * oz));
    float Tn0 = fmaf(R[0], t3x, fmaf(R[1], t3y, fmaf(R[2], t3z, T[0])));
    float Tn1 = fmaf(R[3], t3x, fmaf(R[4], t3y, fmaf(R[5], t3z, T[1])));
    float Tn2 = fmaf(R[6], t3x, fmaf(R[7], t3y, fmaf(R[8], t3z, T[2])));
    float Rn[9];
#pragma unroll
    for (int r = 0; r < 3; r++)
#pragma unroll
        for (int k = 0; k < 3; k++)
            Rn[r * 3 + k] = fmaf(R[r * 3 + 0], rc[k],
                            fmaf(R[r * 3 + 1], rc[3 + k],
                                 R[r * 3 + 2] * rc[6 + k]));
#pragma unroll
    for (int i = 0; i < 9; i++) R[i] = Rn[i];
    T[0] = Tn0; T[1] = Tn1; T[2] = Tn2;
    if (store) {
        orow[c * 3 + 0] = Tn0;
        orow[c * 3 + 1] = Tn1;
        orow[c * 3 + 2] = Tn2;
    }
}

__global__ __launch_bounds__(TPB, 8) void skeleton_fk_kernel(
    const float* __restrict__ angles,
    const float* __restrict__ xyz,
    float* __restrict__ out,
    int B)
{
    __shared__ float sm[XOFF_SZ + ROWS * RROW];
    float* xoff = sm;            // [24*3] bone offsets (root slot = abs pos)
    float* rows = sm + XOFF_SZ;  // [32][217]

    const int t    = threadIdx.x;
    const int wid  = t >> 5;
    const int lane = t & 31;
    const int b0   = blockIdx.x * ROWS;
    const int nvalid = min(ROWS, B - b0);

    // ---- bone offsets into smem (broadcast-read later) ----
    if (t < 24) {
        int p = c_parent[t];
        float x = __ldg(xyz + t * 3 + 0);
        float y = __ldg(xyz + t * 3 + 1);
        float z = __ldg(xyz + t * 3 + 2);
        if (p >= 0) {
            x -= __ldg(xyz + p * 3 + 0);
            y -= __ldg(xyz + p * 3 + 1);
            z -= __ldg(xyz + p * 3 + 2);
        }
        xoff[t * 3 + 0] = x;
        xoff[t * 3 + 1] = y;
        xoff[t * 3 + 2] = z;
    }

    // ---- coalesced load: 32 rows x 36 float4 = 1152 float4 ----
    {
        const float4* __restrict__ g4 =
            reinterpret_cast<const float4*>(angles) + (size_t)b0 * 36;
        const int total4 = nvalid * 36;
#pragma unroll
        for (int it = 0; it < 9; it++) {
            int idx = it * TPB + t;
            if (idx < total4) {
                float4 v = g4[idx];
                int row  = idx / 36;
                int col4 = idx % 36;
                float* dst = rows + row * RROW + col4 * 4;
                dst[0] = v.x; dst[1] = v.y; dst[2] = v.z; dst[3] = v.w;
            }
        }
    }
    __syncthreads();

    // ---- compute: lane -> row, warp -> role ----
    if (lane < nvalid) {
        const float* srow = rows + lane * RROW;        // angles
        float*       orow = rows + lane * RROW + 144;  // compact T output [24*3]
        float R[9], T[3];

        if (wid == 0) {            // role A
            float R0[9], T0[3];
            fk_root(srow, orow, xoff, R0, T0, true);
#pragma unroll
            for (int i = 0; i < 9; i++) R[i] = R0[i];
            T[0] = T0[0]; T[1] = T0[1]; T[2] = T0[2];
            fk_step(srow, orow, xoff, 1,  R, T, true);
            fk_step(srow, orow, xoff, 4,  R, T, true);
            fk_step(srow, orow, xoff, 7,  R, T, true);
            fk_step(srow, orow, xoff, 10, R, T, true);
#pragma unroll
            for (int i = 0; i < 9; i++) R[i] = R0[i];
            T[0] = T0[0]; T[1] = T0[1]; T[2] = T0[2];
            fk_step(srow, orow, xoff, 2,  R, T, true);
            fk_step(srow, orow, xoff, 5,  R, T, true);
            fk_step(srow, orow, xoff, 8,  R, T, true);
            fk_step(srow, orow, xoff, 11, R, T, true);
        } else if (wid == 1) {     // role B
            fk_root(srow, orow, xoff, R, T, false);
            fk_step(srow, orow, xoff, 3,  R, T, true);
            fk_step(srow, orow, xoff, 6,  R, T, true);
            fk_step(srow, orow, xoff, 9,  R, T, true);
            fk_step(srow, orow, xoff, 12, R, T, true);
            fk_step(srow, orow, xoff, 15, R, T, true);
        } else if (wid == 2) {     // role C
            fk_root(srow, orow, xoff, R, T, false);
            fk_step(srow, orow, xoff, 3,  R, T, false);
            fk_step(srow, orow, xoff, 6,  R, T, false);
            fk_step(srow, orow, xoff, 9,  R, T, false);
            fk_step(srow, orow, xoff, 13, R, T, true);
            fk_step(srow, orow, xoff, 16, R, T, true);
            fk_step(srow, orow, xoff, 18, R, T, true);
            fk_step(srow, orow, xoff, 20, R, T, true);
            fk_step(srow, orow, xoff, 22, R, T, true);
        } else {                   // role D
            fk_root(srow, orow, xoff, R, T, false);
            fk_step(srow, orow, xoff, 3,  R, T, false);
            fk_step(srow, orow, xoff, 6,  R, T, false);
            fk_step(srow, orow, xoff, 9,  R, T, false);
            fk_step(srow, orow, xoff, 14, R, T, true);
            fk_step(srow, orow, xoff, 17, R, T, true);
            fk_step(srow, orow, xoff, 19, R, T, true);
            fk_step(srow, orow, xoff, 21, R, T, true);
            fk_step(srow, orow, xoff, 23, R, T, true);
        }
    }
    __syncthreads();

    // ---- coalesced store: 32 rows x 18 float4 = 576 float4 ----
    {
        float4* __restrict__ o4 =
            reinterpret_cast<float4*>(out) + (size_t)b0 * 18;
        const int total4 = nvalid * 18;
#pragma unroll
        for (int it = 0; it < 5; it++) {
            int idx = it * TPB + t;
            if (idx < total4) {
                int row  = idx / 18;
                int col4 = idx % 18;
                const float* orow = rows + row * RROW + 144 + col4 * 4;
                float4 v;
                v.x = orow[0]; v.y = orow[1]; v.z = orow[2]; v.w = orow[3];
                o4[idx] = v;
            }
        }
    }
}

extern "C" void kernel_launch(void* const* d_in, const int* in_sizes, int n_in,
                              void* d_out, int out_size) {
    const float* angles = (const float*)d_in[0];
    const float* xyz    = (const float*)d_in[1];
    float* out          = (float*)d_out;
    const int B = in_sizes[0] / (24 * 6);
    const int blocks = (B + ROWS - 1) / ROWS;
    skeleton_fk_kernel<<<blocks, TPB>>>(angles, xyz, out, B);
}